// round 7
// baseline (speedup 1.0000x reference)
#include <cuda_runtime.h>
#include <cstdint>

#define L_LEN   65536
#define L_MASK  (L_LEN - 1)
#define CIN     8
#define COUT    8
#define FS      4
#define TPB     128
#define TILE    512
#define ROWF    516        // 512 + 4 halo floats, 16B-aligned row stride
#define TPB_TILES 4        // tiles per block (2048 positions)

// ---- packed f32x2 helpers (Blackwell sm_100a+) ------------------------------
__device__ __forceinline__ float2 ffma2(float2 a, float2 b, float2 c) {
    float2 d;
    asm("fma.rn.f32x2 %0, %1, %2, %3;"
        : "=l"(reinterpret_cast<unsigned long long&>(d))
        : "l"(reinterpret_cast<const unsigned long long&>(a)),
          "l"(reinterpret_cast<const unsigned long long&>(b)),
          "l"(reinterpret_cast<const unsigned long long&>(c)));
    return d;
}

__device__ __forceinline__ float2 dup2(float x) {
    float2 d;
    asm("mov.b64 %0, {%1, %1};"
        : "=l"(reinterpret_cast<unsigned long long&>(d))
        : "f"(x));
    return d;
}

__device__ __forceinline__ uint32_t smem_u32(const void* p) {
    uint32_t a;
    asm("{ .reg .u64 t; cvta.to.shared.u64 t, %1; cvt.u32.u64 %0, t; }"
        : "=r"(a) : "l"(p));
    return a;
}

__device__ __forceinline__ void cp_async16(uint32_t dst, const float* src) {
    asm volatile("cp.async.cg.shared.global [%0], [%1], 16;"
                 :: "r"(dst), "l"(src));
}

// ----------------------------------------------------------------------------
// out[b, co, l] = bias[co] + sum_{ci,k} x[b, ci, (l+k) mod L] * W[co, ci, k]
//
// Block: 4 consecutive 512-position tiles of one batch, rolling 2-buffer
// cp.async pipeline with a constant 1-tile look-ahead: tile i+2's loads are
// issued right after tile i's compute, so after the prologue no DRAM latency
// is ever exposed. Thread t owns positions [4t, 4t+4): conflict-free LDS.128
// windows, coalesced STG.128 stores, all 8 co as 4 f32x2-packed pairs.
// ----------------------------------------------------------------------------
__global__ __launch_bounds__(TPB, 6)
void conv_pbc_kernel(const float* __restrict__ x,
                     const float* __restrict__ W,
                     const float* __restrict__ bias,
                     float* __restrict__ out)
{
    __shared__ float  xs[2][CIN][ROWF];
    __shared__ float2 w2s[CIN][FS][COUT / 2];   // (W[2cp,ci,k], W[2cp+1,ci,k])
    __shared__ float2 b2s[COUT / 2];

    const int t = threadIdx.x;

    // weights / bias into SMEM (128 packed entries, one per thread);
    // visible to compute after the first __syncthreads in the loop.
    {
        const int cp = t & 3;
        const int k  = (t >> 2) & 3;
        const int ci = (t >> 4) & 7;
        w2s[ci][k][cp] = make_float2(W[(2 * cp)     * CIN * FS + ci * FS + k],
                                     W[(2 * cp + 1) * CIN * FS + ci * FS + k]);
    }
    if (t < COUT / 2)
        b2s[t] = make_float2(bias[2 * t], bias[2 * t + 1]);

    const int b     = blockIdx.x >> 5;           // 32 groups per batch
    const int base0 = (blockIdx.x & 31) << 11;   // group start (4 * 512)

    const float* __restrict__ xb = x   + (size_t)b * CIN  * L_LEN;
    float*       __restrict__ ob = out + (size_t)b * COUT * L_LEN;

    const uint32_t xs_base = smem_u32(&xs[0][0][0]);

    // issue all cp.asyncs for tile `i` (positions base0 + 512*i) into buffer buf
    auto issue_tile = [&](int i, int buf) {
        const int base = base0 + TILE * i;
        const uint32_t dst0 =
            xs_base + (uint32_t)buf * (CIN * ROWF * 4) + 16u * t;
        #pragma unroll
        for (int ci = 0; ci < CIN; ++ci)
            cp_async16(dst0 + ci * (ROWF * 4),
                       xb + (size_t)ci * L_LEN + base + 4 * t);
        if (t < CIN)   // halo: next 4 floats, circular (always 16B aligned)
            cp_async16(xs_base + (uint32_t)buf * (CIN * ROWF * 4)
                               + t * (ROWF * 4) + TILE * 4,
                       xb + (size_t)t * L_LEN + ((base + TILE) & L_MASK));
    };

    // compute + store one resident tile from buffer buf
    auto do_tile = [&](int i, int buf) {
        const int base = base0 + TILE * i;

        float2 acc[4][COUT / 2];
        {
            const float2 c0 = b2s[0], c1 = b2s[1], c2 = b2s[2], c3 = b2s[3];
            #pragma unroll
            for (int q = 0; q < 4; ++q) {
                acc[q][0] = c0; acc[q][1] = c1; acc[q][2] = c2; acc[q][3] = c3;
            }
        }

        #pragma unroll
        for (int ci = 0; ci < CIN; ++ci) {
            float2 wv[FS][COUT / 2];
            #pragma unroll
            for (int k = 0; k < FS; ++k)
                #pragma unroll
                for (int cp = 0; cp < 4; ++cp)
                    wv[k][cp] = w2s[ci][k][cp];

            float xw[8];
            {
                const float4 a0 =
                    *reinterpret_cast<const float4*>(&xs[buf][ci][4 * t]);
                const float4 a1 =
                    *reinterpret_cast<const float4*>(&xs[buf][ci][4 * t + 4]);
                xw[0] = a0.x; xw[1] = a0.y; xw[2] = a0.z; xw[3] = a0.w;
                xw[4] = a1.x; xw[5] = a1.y; xw[6] = a1.z; xw[7] = a1.w;
            }

            #pragma unroll
            for (int i2 = 0; i2 < 7; ++i2) {
                const float2 xk = dup2(xw[i2]);
                #pragma unroll
                for (int k = 0; k < FS; ++k) {
                    const int q = i2 - k;
                    if (q >= 0 && q < 4) {
                        #pragma unroll
                        for (int cp = 0; cp < 4; ++cp)
                            acc[q][cp] = ffma2(wv[k][cp], xk, acc[q][cp]);
                    }
                }
            }
        }

        float* __restrict__ op = ob + base + 4 * t;
        #pragma unroll
        for (int cp = 0; cp < 4; ++cp) {
            float4 v;
            v.x = acc[0][cp].x; v.y = acc[1][cp].x;
            v.z = acc[2][cp].x; v.w = acc[3][cp].x;
            *reinterpret_cast<float4*>(op + (size_t)(2 * cp) * L_LEN) = v;
            v.x = acc[0][cp].y; v.y = acc[1][cp].y;
            v.z = acc[2][cp].y; v.w = acc[3][cp].y;
            *reinterpret_cast<float4*>(op + (size_t)(2 * cp + 1) * L_LEN) = v;
        }
    };

    // prologue: tiles 0 and 1 in flight
    issue_tile(0, 0);
    asm volatile("cp.async.commit_group;");
    issue_tile(1, 1);
    asm volatile("cp.async.commit_group;");

    // steady state: one commit per iteration keeps wait_group 1 exact
    #pragma unroll
    for (int i = 0; i < TPB_TILES; ++i) {
        const int buf = i & 1;
        asm volatile("cp.async.wait_group 1;");
        __syncthreads();                 // tile i resident (+ weights visible)

        do_tile(i, buf);

        __syncthreads();                 // all reads of xs[buf] done
        if (i + 2 < TPB_TILES)
            issue_tile(i + 2, buf);
        asm volatile("cp.async.commit_group;");   // possibly empty group
    }
}

extern "C" void kernel_launch(void* const* d_in, const int* in_sizes, int n_in,
                              void* d_out, int out_size)
{
    const float* x    = (const float*)d_in[0];  // (64, 8, 65536)
    const float* W    = (const float*)d_in[1];  // (8, 8, 4)
    const float* bias = (const float*)d_in[2];  // (8,)
    float* out        = (float*)d_out;          // (64, 8, 65536)

    // 64 batches * 32 groups (4 tiles of 512) = 2048 blocks of 128 threads
    conv_pbc_kernel<<<64 * (L_LEN / (TPB_TILES * TILE)), TPB>>>(x, W, bias, out);
}